// round 14
// baseline (speedup 1.0000x reference)
#include <cuda_runtime.h>
#include <cuda_fp16.h>
#include <cstdint>

#define BATCH   2
#define SEQ     2048
#define CDIM    768
#define HEADS   12
#define HDIM    64
#define QKV_N   2304
#define MROWS   4096
#define BH      24
#define SCALEF  0.125f
#define LOG2E   1.4426950408889634f

// ---------------------------------------------------------------------------
// Scratch (pure fp16)
// ---------------------------------------------------------------------------
__device__ __half g_x_hi[MROWS * CDIM];
__device__ __half g_wqkv_hi[QKV_N * CDIM];
__device__ __half g_wproj_hi[CDIM * CDIM];
__device__ __half g_q_hi[BH * SEQ * HDIM];    // [b,h,n,d], pre-scaled by log2e/8
__device__ __half g_k_hi[BH * SEQ * HDIM];
__device__ __half g_vt_hi[BH * HDIM * SEQ];   // [b,h,d,n]
__device__ __half g_ctx_hi[MROWS * CDIM];

// ---------------------------------------------------------------------------
// Helpers
// ---------------------------------------------------------------------------
__device__ __forceinline__ uint32_t smem_u32(const void* p) {
    uint32_t a;
    asm("{ .reg .u64 t; cvta.to.shared.u64 t, %1; cvt.u32.u64 %0, t; }" : "=r"(a) : "l"(p));
    return a;
}
__device__ __forceinline__ void cp16(uint32_t dst, const void* src) {
    asm volatile("cp.async.cg.shared.global [%0], [%1], 16;" :: "r"(dst), "l"(src));
}
__device__ __forceinline__ void cp_commit() { asm volatile("cp.async.commit_group;"); }
template <int N> __device__ __forceinline__ void cp_wait() {
    asm volatile("cp.async.wait_group %0;" :: "n"(N));
}
__device__ __forceinline__ void ldsm4(uint32_t a, uint32_t& r0, uint32_t& r1, uint32_t& r2, uint32_t& r3) {
    asm volatile("ldmatrix.sync.aligned.m8n8.x4.shared.b16 {%0,%1,%2,%3}, [%4];"
                 : "=r"(r0), "=r"(r1), "=r"(r2), "=r"(r3) : "r"(a));
}
__device__ __forceinline__ void mma_f32(float* c, const uint32_t* a, const uint32_t* b) {
    asm volatile("mma.sync.aligned.m16n8k16.row.col.f32.f16.f16.f32 "
                 "{%0,%1,%2,%3}, {%4,%5,%6,%7}, {%8,%9}, {%0,%1,%2,%3};"
                 : "+f"(c[0]), "+f"(c[1]), "+f"(c[2]), "+f"(c[3])
                 : "r"(a[0]), "r"(a[1]), "r"(a[2]), "r"(a[3]), "r"(b[0]), "r"(b[1]));
}
__device__ __forceinline__ uint32_t pack2h(float x, float y) {
    __half2 H = __halves2half2(__float2half_rn(x), __float2half_rn(y));
    return *reinterpret_cast<uint32_t*>(&H);
}
__device__ __forceinline__ float fexp2(float x) {
    float r;
    asm("ex2.approx.f32 %0, %1;" : "=f"(r) : "f"(x));
    return r;
}

// ---------------------------------------------------------------------------
// Converts: one launch covers all three arrays
// ---------------------------------------------------------------------------
__global__ void convert_all(const float* __restrict__ s0, __half* __restrict__ d0, int n0,
                            const float* __restrict__ s1, __half* __restrict__ d1, int n1,
                            const float* __restrict__ s2, __half* __restrict__ d2, int n2)
{
    const int ntot = n0 + n1 + n2;
    for (int i = blockIdx.x * blockDim.x + threadIdx.x; i < ntot; i += gridDim.x * blockDim.x) {
        if (i < n0)               d0[i] = __float2half_rn(s0[i]);
        else if (i < n0 + n1)     d1[i - n0] = __float2half_rn(s1[i - n0]);
        else                      d2[i - n0 - n1] = __float2half_rn(s2[i - n0 - n1]);
    }
}

// ---------------------------------------------------------------------------
// GEMM core (round-10 proven shape): C(128x128) = Ah Bh^T over K=768,
// K-chunk 32, 2-stage pipeline. 256 threads, warp tile 64x32. 80B row pitch.
// ---------------------------------------------------------------------------
#define GSTAGE   20480
#define G_BHI    10240
#define GEMM_SMEM (2 * GSTAGE)

__device__ __forceinline__ void gemm_load_stage(
    uint32_t sb, const __half* Ahi, const __half* Bhi,
    int m0, int n0, int k0, int tid)
{
    const int row = tid >> 1;
    const int cb  = (tid & 1) * 32;
    const size_t ga = (size_t)(m0 + row) * CDIM + k0;
    const size_t gb = (size_t)(n0 + row) * CDIM + k0;
    const uint32_t so = (uint32_t)row * 80 + cb;
    cp16(sb + so,               (const char*)(Ahi + ga) + cb);
    cp16(sb + so + 16,          (const char*)(Ahi + ga) + cb + 16);
    cp16(sb + G_BHI + so,       (const char*)(Bhi + gb) + cb);
    cp16(sb + G_BHI + so + 16,  (const char*)(Bhi + gb) + cb + 16);
}

__device__ __forceinline__ void ld_afrag(uint32_t st, int wm, int step,
                                         uint32_t a_lrow, uint32_t a_koff, uint32_t* a)
{
    const int ks = step >> 2, mf = step & 3;
    uint32_t addr = st + (uint32_t)(wm * 64 + mf * 16 + a_lrow) * 80 + ks * 32 + a_koff;
    ldsm4(addr, a[0], a[1], a[2], a[3]);
}
__device__ __forceinline__ void ld_bfrag(uint32_t st, int wn, int ks,
                                         uint32_t b_lrow, uint32_t b_koff,
                                         uint32_t bh[4][2])
{
#pragma unroll
    for (int nfp = 0; nfp < 2; nfp++) {
        uint32_t addr = st + G_BHI + (uint32_t)(wn * 32 + nfp * 16 + b_lrow) * 80 + ks * 32 + b_koff;
        ldsm4(addr, bh[2 * nfp][0], bh[2 * nfp][1], bh[2 * nfp + 1][0], bh[2 * nfp + 1][1]);
    }
}

__device__ __forceinline__ void gemm_core(
    char* smem, const __half* Ahi, const __half* Bhi,
    int m0, int n0, float c[4][4][4])
{
    const int tid = threadIdx.x;
    const int lane = tid & 31;
    const int wid = tid >> 5;
    const int wm = wid >> 2, wn = wid & 3;
    const uint32_t sb = smem_u32(smem);

    const uint32_t a_lrow = lane % 16, a_koff = (lane >> 4) * 16;
    const uint32_t b_lrow = (lane % 8) + ((lane >> 4) << 3), b_koff = ((lane >> 3) & 1) * 16;

#pragma unroll
    for (int i = 0; i < 4; i++)
#pragma unroll
        for (int j = 0; j < 4; j++)
#pragma unroll
            for (int e = 0; e < 4; e++) c[i][j][e] = 0.0f;

    gemm_load_stage(sb, Ahi, Bhi, m0, n0, 0, tid);
    cp_commit();

    uint32_t ar[2][4];
    uint32_t bhr[2][4][2];

    for (int it = 0; it < 24; it++) {
        cp_wait<0>();
        __syncthreads();
        if (it + 1 < 24) {
            gemm_load_stage(sb + ((it + 1) & 1) * GSTAGE, Ahi, Bhi, m0, n0, (it + 1) * 32, tid);
            cp_commit();
        }
        const uint32_t st = sb + (it & 1) * GSTAGE;

        ld_bfrag(st, wn, 0, b_lrow, b_koff, bhr[0]);
        ld_afrag(st, wm, 0, a_lrow, a_koff, ar[0]);

#pragma unroll
        for (int ks = 0; ks < 2; ks++) {
            if (ks == 0)
                ld_bfrag(st, wn, 1, b_lrow, b_koff, bhr[1]);
#pragma unroll
            for (int mf = 0; mf < 4; mf++) {
                const int step = ks * 4 + mf;
                if (step + 1 < 8)
                    ld_afrag(st, wm, step + 1, a_lrow, a_koff, ar[(step + 1) & 1]);
                const uint32_t* a = ar[step & 1];
#pragma unroll
                for (int nf = 0; nf < 4; nf++)
                    mma_f32(c[mf][nf], a, bhr[ks][nf]);
            }
        }
    }
}

// ---------------------------------------------------------------------------
// QKV GEMM: grid (18, 32), 256 threads, 2 CTAs/SM
// ---------------------------------------------------------------------------
__device__ __forceinline__ void qkv_store(int s, int rowg, int colg, float v0, float v1)
{
    const int b = rowg >> 11, n = rowg & 2047;
    const int rem = colg - s * CDIM;
    const int h = rem >> 6, d = rem & 63;
    if (s == 0) {
        const float qs = SCALEF * LOG2E;    // fold softmax scale + log2e into q
        const size_t off = ((size_t)(b * HEADS + h) * SEQ + n) * HDIM + d;
        *reinterpret_cast<uint32_t*>(g_q_hi + off) = pack2h(v0 * qs, v1 * qs);
    } else if (s == 1) {
        const size_t off = ((size_t)(b * HEADS + h) * SEQ + n) * HDIM + d;
        *reinterpret_cast<uint32_t*>(g_k_hi + off) = pack2h(v0, v1);
    } else {
        const size_t base = ((size_t)(b * HEADS + h) * HDIM) * SEQ;
        g_vt_hi[base + (size_t)d * SEQ + n]       = __float2half_rn(v0);
        g_vt_hi[base + (size_t)(d + 1) * SEQ + n] = __float2half_rn(v1);
    }
}

__global__ __launch_bounds__(256, 2) void qkv_mma()
{
    extern __shared__ char smem[];
    const int n0 = blockIdx.x * 128;
    const int m0 = blockIdx.y * 128;
    const int lane = threadIdx.x & 31;
    const int wid = threadIdx.x >> 5;
    const int wm = wid >> 2, wn = wid & 3;

    float c[4][4][4];
    gemm_core(smem, g_x_hi, g_wqkv_hi, m0, n0, c);

    const int s = n0 / CDIM;
#pragma unroll
    for (int mf = 0; mf < 4; mf++)
#pragma unroll
        for (int nf = 0; nf < 4; nf++) {
            const int rg = m0 + wm * 64 + mf * 16 + (lane >> 2);
            const int cg = n0 + wn * 32 + nf * 8 + (lane & 3) * 2;
            qkv_store(s, rg,     cg, c[mf][nf][0], c[mf][nf][1]);
            qkv_store(s, rg + 8, cg, c[mf][nf][2], c[mf][nf][3]);
        }
}

// ---------------------------------------------------------------------------
// Output projection: grid (6, 32), 256 threads, 2 CTAs/SM
// ---------------------------------------------------------------------------
__global__ __launch_bounds__(256, 2) void proj_mma(const float* __restrict__ bias,
                                                   float* __restrict__ out)
{
    extern __shared__ char smem[];
    const int n0 = blockIdx.x * 128;
    const int m0 = blockIdx.y * 128;
    const int lane = threadIdx.x & 31;
    const int wid = threadIdx.x >> 5;
    const int wm = wid >> 2, wn = wid & 3;

    float c[4][4][4];
    gemm_core(smem, g_ctx_hi, g_wproj_hi, m0, n0, c);

#pragma unroll
    for (int mf = 0; mf < 4; mf++)
#pragma unroll
        for (int nf = 0; nf < 4; nf++) {
            const int rg = m0 + wm * 64 + mf * 16 + (lane >> 2);
            const int cg = n0 + wn * 32 + nf * 8 + (lane & 3) * 2;
            const float b0 = bias[cg], b1 = bias[cg + 1];
            float2 v0 = make_float2(c[mf][nf][0] + b0, c[mf][nf][1] + b1);
            float2 v1 = make_float2(c[mf][nf][2] + b0, c[mf][nf][3] + b1);
            *reinterpret_cast<float2*>(out + (size_t)rg * CDIM + cg) = v0;
            *reinterpret_cast<float2*>(out + (size_t)(rg + 8) * CDIM + cg) = v1;
        }
}

// ---------------------------------------------------------------------------
// Flash attention: q-tile 64 rows, 128 threads (4 warps x 16 rows), 4 CTAs/SM.
// grid (SEQ/64=32, BH=24). Base-2 softmax (log2e folded into q).
// smem: Q 64x144 = 9216 | 2 stages x [K 64x144 = 9216 | V 64x144 = 9216]
// ---------------------------------------------------------------------------
#define AQ       9216
#define ASTAGE   18432
#define AV_HI    9216
#define ATTN_SMEM (AQ + 2 * ASTAGE)    // 46080

__device__ __forceinline__ void attn_load_stage(
    uint32_t sb, const __half* Kh, const __half* Vh, int kv0, int tid)
{
    // tid 0..63 -> K row tid; tid 64..127 -> V row (tid-64). Full 128B row each.
    const int half = tid >> 6;
    const int row = tid & 63;
    const char* src = half ? (const char*)(Vh + (size_t)row * SEQ + kv0)
                           : (const char*)(Kh + (size_t)(kv0 + row) * HDIM);
    const uint32_t so = (half ? AV_HI : 0u) + (uint32_t)row * 144;
#pragma unroll
    for (int u = 0; u < 8; u++) cp16(sb + so + u * 16, src + u * 16);
}

__global__ __launch_bounds__(128, 4) void attn_mma()
{
    extern __shared__ char smem[];
    const uint32_t sb = smem_u32(smem);
    const int q0 = blockIdx.x * 64;
    const int bh = blockIdx.y;
    const int tid = threadIdx.x;
    const int lane = tid & 31;
    const int wid = tid >> 5;          // 0..3

    const __half* Qh = g_q_hi + (size_t)bh * SEQ * HDIM;
    const __half* Kh = g_k_hi + (size_t)bh * SEQ * HDIM;
    const __half* Vh = g_vt_hi + (size_t)bh * HDIM * SEQ;

    // Load Q tile: 64 rows x 128B, 2 threads per row
    {
        const int row = tid >> 1;
        const int cb = (tid & 1) * 64;
        const uint4* qs = reinterpret_cast<const uint4*>((const char*)(Qh + (size_t)(q0 + row) * HDIM) + cb);
        uint4* dh = reinterpret_cast<uint4*>(smem + (uint32_t)row * 144 + cb);
#pragma unroll
        for (int i = 0; i < 4; i++) dh[i] = qs[i];
    }
    attn_load_stage(sb + AQ, Kh, Vh, 0, tid);
    cp_commit();
    __syncthreads();

    const uint32_t a_lrow = lane % 16, a_koff = (lane >> 4) * 16;
    const uint32_t b_lrow = (lane % 8) + ((lane >> 4) << 3), b_koff = ((lane >> 3) & 1) * 16;

    uint32_t qh[4][4];
#pragma unroll
    for (int ks = 0; ks < 4; ks++) {
        uint32_t addr = sb + (uint32_t)(wid * 16 + a_lrow) * 144 + ks * 32 + a_koff;
        ldsm4(addr, qh[ks][0], qh[ks][1], qh[ks][2], qh[ks][3]);
    }

    float o[8][4];
#pragma unroll
    for (int nf = 0; nf < 8; nf++)
#pragma unroll
        for (int e = 0; e < 4; e++) o[nf][e] = 0.0f;
    float m_run0 = -1e30f, m_run1 = -1e30f, l_run0 = 0.0f, l_run1 = 0.0f;

    const int NIT = SEQ / 64;   // 32
    for (int it = 0; it < NIT; it++) {
        cp_wait<0>();
        __syncthreads();
        if (it + 1 < NIT) {
            attn_load_stage(sb + AQ + ((it + 1) & 1) * ASTAGE, Kh, Vh, (it + 1) * 64, tid);
            cp_commit();
        }
        const uint32_t st = sb + AQ + (it & 1) * ASTAGE;

        // ---- S = qh kh^T (scores already in log2 domain) ----
        float s[8][4];
#pragma unroll
        for (int nf = 0; nf < 8; nf++)
#pragma unroll
            for (int e = 0; e < 4; e++) s[nf][e] = 0.0f;
#pragma unroll
        for (int ks = 0; ks < 4; ks++) {
            uint32_t kbh[8][2];
#pragma unroll
            for (int nfp = 0; nfp < 4; nfp++) {
                uint32_t addr = st + (uint32_t)(nfp * 16 + b_lrow) * 144 + ks * 32 + b_koff;
                ldsm4(addr, kbh[2 * nfp][0], kbh[2 * nfp][1], kbh[2 * nfp + 1][0], kbh[2 * nfp + 1][1]);
            }
#pragma unroll
            for (int nf = 0; nf < 8; nf++)
                mma_f32(s[nf], qh[ks], kbh[nf]);
        }

        // ---- online softmax (base-2) ----
        float vm0 = -1e30f, vm1 = -1e30f;
#pragma unroll
        for (int nf = 0; nf < 8; nf++) {
            vm0 = fmaxf(vm0, fmaxf(s[nf][0], s[nf][1]));
            vm1 = fmaxf(vm1, fmaxf(s[nf][2], s[nf][3]));
        }
        vm0 = fmaxf(vm0, __shfl_xor_sync(0xffffffff, vm0, 1));
        vm0 = fmaxf(vm0, __shfl_xor_sync(0xffffffff, vm0, 2));
        vm1 = fmaxf(vm1, __shfl_xor_sync(0xffffffff, vm1, 1));
        vm1 = fmaxf(vm1, __shfl_xor_sync(0xffffffff, vm1, 2));
        const float nm0 = fmaxf(m_run0, vm0);
        const float nm1 = fmaxf(m_run1, vm1);
        const float corr0 = fexp2(m_run0 - nm0);
        const float corr1 = fexp2(m_run1 - nm1);
        float sum0 = 0.0f, sum1 = 0.0f;
#pragma unroll
        for (int nf = 0; nf < 8; nf++) {
            s[nf][0] = fexp2(s[nf][0] - nm0); sum0 += s[nf][0];
            s[nf][1] = fexp2(s[nf][1] - nm0); sum0 += s[nf][1];
            s[nf][2] = fexp2(s[nf][2] - nm1); sum1 += s[nf][2];
            s[nf][3] = fexp2(s[nf][3] - nm1); sum1 += s[nf][3];
        }
        sum0 += __shfl_xor_sync(0xffffffff, sum0, 1);
        sum0 += __shfl_xor_sync(0xffffffff, sum0, 2);
        sum1 += __shfl_xor_sync(0xffffffff, sum1, 1);
        sum1 += __shfl_xor_sync(0xffffffff, sum1, 2);
        l_run0 = l_run0 * corr0 + sum0;
        l_run1 = l_run1 * corr1 + sum1;
        m_run0 = nm0; m_run1 = nm1;
#pragma unroll
        for (int nf = 0; nf < 8; nf++) {
            o[nf][0] *= corr0; o[nf][1] *= corr0;
            o[nf][2] *= corr1; o[nf][3] *= corr1;
        }

        // ---- O += p16 · vh ----
#pragma unroll
        for (int ks2 = 0; ks2 < 4; ks2++) {
            uint32_t pah[4];
            pah[0] = pack2h(s[2 * ks2][0],     s[2 * ks2][1]);
            pah[1] = pack2h(s[2 * ks2][2],     s[2 * ks2][3]);
            pah[2] = pack2h(s[2 * ks2 + 1][0], s[2 * ks2 + 1][1]);
            pah[3] = pack2h(s[2 * ks2 + 1][2], s[2 * ks2 + 1][3]);
            uint32_t vbh[8][2];
#pragma unroll
            for (int nfp = 0; nfp < 4; nfp++) {
                uint32_t addr = st + AV_HI + (uint32_t)(nfp * 16 + b_lrow) * 144 + ks2 * 32 + b_koff;
                ldsm4(addr, vbh[2 * nfp][0], vbh[2 * nfp][1], vbh[2 * nfp + 1][0], vbh[2 * nfp + 1][1]);
            }
#pragma unroll
            for (int nf = 0; nf < 8; nf++)
                mma_f32(o[nf], pah, vbh[nf]);
        }
    }

    // ---- epilogue ----
    const int b = bh / HEADS;
    const int h = bh % HEADS;
    const float inv0 = 1.0f / l_run0;
    const float inv1 = 1.0f / l_run1;
    const int r0 = q0 + wid * 16 + (lane >> 2);
#pragma unroll
    for (int nf = 0; nf < 8; nf++) {
        const int d = nf * 8 + (lane & 3) * 2;
        size_t off = ((size_t)(b * SEQ + r0)) * CDIM + h * HDIM + d;
        *reinterpret_cast<uint32_t*>(g_ctx_hi + off) = pack2h(o[nf][0] * inv0, o[nf][1] * inv0);
        off = ((size_t)(b * SEQ + r0 + 8)) * CDIM + h * HDIM + d;
        *reinterpret_cast<uint32_t*>(g_ctx_hi + off) = pack2h(o[nf][2] * inv1, o[nf][3] * inv1);
    }
}

// ---------------------------------------------------------------------------
// Launch
// ---------------------------------------------------------------------------
extern "C" void kernel_launch(void* const* d_in, const int* in_sizes, int n_in,
                              void* d_out, int out_size)
{
    const float* x      = (const float*)d_in[0];
    const float* w_qkv  = (const float*)d_in[1];
    const float* w_proj = (const float*)d_in[2];
    const float* b_proj = (const float*)d_in[3];
    float* out = (float*)d_out;
    (void)in_sizes; (void)n_in; (void)out_size;

    cudaFuncSetAttribute(qkv_mma,  cudaFuncAttributeMaxDynamicSharedMemorySize, GEMM_SMEM);
    cudaFuncSetAttribute(attn_mma, cudaFuncAttributeMaxDynamicSharedMemorySize, ATTN_SMEM);
    cudaFuncSetAttribute(proj_mma, cudaFuncAttributeMaxDynamicSharedMemorySize, GEMM_SMEM);

    __half *xh, *wh, *ph;
    cudaGetSymbolAddress((void**)&xh, g_x_hi);
    cudaGetSymbolAddress((void**)&wh, g_wqkv_hi);
    cudaGetSymbolAddress((void**)&ph, g_wproj_hi);

    convert_all<<<1024, 256>>>(x, xh, MROWS * CDIM,
                               w_qkv, wh, QKV_N * CDIM,
                               w_proj, ph, CDIM * CDIM);

    qkv_mma<<<dim3(QKV_N / 128, MROWS / 128), 256, GEMM_SMEM>>>();
    attn_mma<<<dim3(SEQ / 64, BH), 128, ATTN_SMEM>>>();
    proj_mma<<<dim3(CDIM / 128, MROWS / 128), 256, GEMM_SMEM>>>(b_proj, out);
}

// round 16
// speedup vs baseline: 1.2883x; 1.2883x over previous
#include <cuda_runtime.h>
#include <cuda_fp16.h>
#include <cstdint>

#define BATCH   2
#define SEQ     2048
#define CDIM    768
#define HEADS   12
#define HDIM    64
#define QKV_N   2304
#define MROWS   4096
#define BH      24
#define SCALEF  0.125f
#define LOG2E   1.4426950408889634f

// ---------------------------------------------------------------------------
// Scratch (pure fp16)
// ---------------------------------------------------------------------------
__device__ __half g_x_hi[MROWS * CDIM];
__device__ __half g_wqkv_hi[QKV_N * CDIM];
__device__ __half g_wproj_hi[CDIM * CDIM];
__device__ __half g_q_hi[BH * SEQ * HDIM];    // [b,h,n,d], pre-scaled by log2e/8
__device__ __half g_k_hi[BH * SEQ * HDIM];
__device__ __half g_vt_hi[BH * HDIM * SEQ];   // [b,h,d,n]
__device__ __half g_ctx_hi[MROWS * CDIM];

// ---------------------------------------------------------------------------
// Helpers
// ---------------------------------------------------------------------------
__device__ __forceinline__ uint32_t smem_u32(const void* p) {
    uint32_t a;
    asm("{ .reg .u64 t; cvta.to.shared.u64 t, %1; cvt.u32.u64 %0, t; }" : "=r"(a) : "l"(p));
    return a;
}
__device__ __forceinline__ void cp16(uint32_t dst, const void* src) {
    asm volatile("cp.async.cg.shared.global [%0], [%1], 16;" :: "r"(dst), "l"(src));
}
__device__ __forceinline__ void cp_commit() { asm volatile("cp.async.commit_group;"); }
template <int N> __device__ __forceinline__ void cp_wait() {
    asm volatile("cp.async.wait_group %0;" :: "n"(N));
}
__device__ __forceinline__ void ldsm4(uint32_t a, uint32_t& r0, uint32_t& r1, uint32_t& r2, uint32_t& r3) {
    asm volatile("ldmatrix.sync.aligned.m8n8.x4.shared.b16 {%0,%1,%2,%3}, [%4];"
                 : "=r"(r0), "=r"(r1), "=r"(r2), "=r"(r3) : "r"(a));
}
__device__ __forceinline__ void mma_f32(float* c, const uint32_t* a, const uint32_t* b) {
    asm volatile("mma.sync.aligned.m16n8k16.row.col.f32.f16.f16.f32 "
                 "{%0,%1,%2,%3}, {%4,%5,%6,%7}, {%8,%9}, {%0,%1,%2,%3};"
                 : "+f"(c[0]), "+f"(c[1]), "+f"(c[2]), "+f"(c[3])
                 : "r"(a[0]), "r"(a[1]), "r"(a[2]), "r"(a[3]), "r"(b[0]), "r"(b[1]));
}
__device__ __forceinline__ uint32_t pack2h(float x, float y) {
    __half2 H = __halves2half2(__float2half_rn(x), __float2half_rn(y));
    return *reinterpret_cast<uint32_t*>(&H);
}
__device__ __forceinline__ float fexp2(float x) {
    float r;
    asm("ex2.approx.f32 %0, %1;" : "=f"(r) : "f"(x));
    return r;
}

// ---------------------------------------------------------------------------
// Converts: one launch covers all three arrays
// ---------------------------------------------------------------------------
__global__ void convert_all(const float* __restrict__ s0, __half* __restrict__ d0, int n0,
                            const float* __restrict__ s1, __half* __restrict__ d1, int n1,
                            const float* __restrict__ s2, __half* __restrict__ d2, int n2)
{
    const int ntot = n0 + n1 + n2;
    for (int i = blockIdx.x * blockDim.x + threadIdx.x; i < ntot; i += gridDim.x * blockDim.x) {
        if (i < n0)               d0[i] = __float2half_rn(s0[i]);
        else if (i < n0 + n1)     d1[i - n0] = __float2half_rn(s1[i - n0]);
        else                      d2[i - n0 - n1] = __float2half_rn(s2[i - n0 - n1]);
    }
}

// ---------------------------------------------------------------------------
// GEMM core (round-10 proven shape): C(128x128) = Ah Bh^T over K=768,
// K-chunk 32, 2-stage pipeline. 256 threads, warp tile 64x32. 80B row pitch.
// ---------------------------------------------------------------------------
#define GSTAGE   20480
#define G_BHI    10240
#define GEMM_SMEM (2 * GSTAGE)

__device__ __forceinline__ void gemm_load_stage(
    uint32_t sb, const __half* Ahi, const __half* Bhi,
    int m0, int n0, int k0, int tid)
{
    const int row = tid >> 1;
    const int cb  = (tid & 1) * 32;
    const size_t ga = (size_t)(m0 + row) * CDIM + k0;
    const size_t gb = (size_t)(n0 + row) * CDIM + k0;
    const uint32_t so = (uint32_t)row * 80 + cb;
    cp16(sb + so,               (const char*)(Ahi + ga) + cb);
    cp16(sb + so + 16,          (const char*)(Ahi + ga) + cb + 16);
    cp16(sb + G_BHI + so,       (const char*)(Bhi + gb) + cb);
    cp16(sb + G_BHI + so + 16,  (const char*)(Bhi + gb) + cb + 16);
}

__device__ __forceinline__ void ld_afrag(uint32_t st, int wm, int step,
                                         uint32_t a_lrow, uint32_t a_koff, uint32_t* a)
{
    const int ks = step >> 2, mf = step & 3;
    uint32_t addr = st + (uint32_t)(wm * 64 + mf * 16 + a_lrow) * 80 + ks * 32 + a_koff;
    ldsm4(addr, a[0], a[1], a[2], a[3]);
}
__device__ __forceinline__ void ld_bfrag(uint32_t st, int wn, int ks,
                                         uint32_t b_lrow, uint32_t b_koff,
                                         uint32_t bh[4][2])
{
#pragma unroll
    for (int nfp = 0; nfp < 2; nfp++) {
        uint32_t addr = st + G_BHI + (uint32_t)(wn * 32 + nfp * 16 + b_lrow) * 80 + ks * 32 + b_koff;
        ldsm4(addr, bh[2 * nfp][0], bh[2 * nfp][1], bh[2 * nfp + 1][0], bh[2 * nfp + 1][1]);
    }
}

__device__ __forceinline__ void gemm_core(
    char* smem, const __half* Ahi, const __half* Bhi,
    int m0, int n0, float c[4][4][4])
{
    const int tid = threadIdx.x;
    const int lane = tid & 31;
    const int wid = tid >> 5;
    const int wm = wid >> 2, wn = wid & 3;
    const uint32_t sb = smem_u32(smem);

    const uint32_t a_lrow = lane % 16, a_koff = (lane >> 4) * 16;
    const uint32_t b_lrow = (lane % 8) + ((lane >> 4) << 3), b_koff = ((lane >> 3) & 1) * 16;

#pragma unroll
    for (int i = 0; i < 4; i++)
#pragma unroll
        for (int j = 0; j < 4; j++)
#pragma unroll
            for (int e = 0; e < 4; e++) c[i][j][e] = 0.0f;

    gemm_load_stage(sb, Ahi, Bhi, m0, n0, 0, tid);
    cp_commit();

    uint32_t ar[2][4];
    uint32_t bhr[2][4][2];

    for (int it = 0; it < 24; it++) {
        cp_wait<0>();
        __syncthreads();
        if (it + 1 < 24) {
            gemm_load_stage(sb + ((it + 1) & 1) * GSTAGE, Ahi, Bhi, m0, n0, (it + 1) * 32, tid);
            cp_commit();
        }
        const uint32_t st = sb + (it & 1) * GSTAGE;

        ld_bfrag(st, wn, 0, b_lrow, b_koff, bhr[0]);
        ld_afrag(st, wm, 0, a_lrow, a_koff, ar[0]);

#pragma unroll
        for (int ks = 0; ks < 2; ks++) {
            if (ks == 0)
                ld_bfrag(st, wn, 1, b_lrow, b_koff, bhr[1]);
#pragma unroll
            for (int mf = 0; mf < 4; mf++) {
                const int step = ks * 4 + mf;
                if (step + 1 < 8)
                    ld_afrag(st, wm, step + 1, a_lrow, a_koff, ar[(step + 1) & 1]);
                const uint32_t* a = ar[step & 1];
#pragma unroll
                for (int nf = 0; nf < 4; nf++)
                    mma_f32(c[mf][nf], a, bhr[ks][nf]);
            }
        }
    }
}

// ---------------------------------------------------------------------------
// QKV GEMM: grid (18, 32), 256 threads, 2 CTAs/SM
// ---------------------------------------------------------------------------
__device__ __forceinline__ void qkv_store(int s, int rowg, int colg, float v0, float v1)
{
    const int b = rowg >> 11, n = rowg & 2047;
    const int rem = colg - s * CDIM;
    const int h = rem >> 6, d = rem & 63;
    if (s == 0) {
        const float qs = SCALEF * LOG2E;    // fold softmax scale + log2e into q
        const size_t off = ((size_t)(b * HEADS + h) * SEQ + n) * HDIM + d;
        *reinterpret_cast<uint32_t*>(g_q_hi + off) = pack2h(v0 * qs, v1 * qs);
    } else if (s == 1) {
        const size_t off = ((size_t)(b * HEADS + h) * SEQ + n) * HDIM + d;
        *reinterpret_cast<uint32_t*>(g_k_hi + off) = pack2h(v0, v1);
    } else {
        const size_t base = ((size_t)(b * HEADS + h) * HDIM) * SEQ;
        g_vt_hi[base + (size_t)d * SEQ + n]       = __float2half_rn(v0);
        g_vt_hi[base + (size_t)(d + 1) * SEQ + n] = __float2half_rn(v1);
    }
}

__global__ __launch_bounds__(256, 2) void qkv_mma()
{
    extern __shared__ char smem[];
    const int n0 = blockIdx.x * 128;
    const int m0 = blockIdx.y * 128;
    const int lane = threadIdx.x & 31;
    const int wid = threadIdx.x >> 5;
    const int wm = wid >> 2, wn = wid & 3;

    float c[4][4][4];
    gemm_core(smem, g_x_hi, g_wqkv_hi, m0, n0, c);

    const int s = n0 / CDIM;
#pragma unroll
    for (int mf = 0; mf < 4; mf++)
#pragma unroll
        for (int nf = 0; nf < 4; nf++) {
            const int rg = m0 + wm * 64 + mf * 16 + (lane >> 2);
            const int cg = n0 + wn * 32 + nf * 8 + (lane & 3) * 2;
            qkv_store(s, rg,     cg, c[mf][nf][0], c[mf][nf][1]);
            qkv_store(s, rg + 8, cg, c[mf][nf][2], c[mf][nf][3]);
        }
}

// ---------------------------------------------------------------------------
// Output projection: grid (6, 32), 256 threads, 2 CTAs/SM
// ---------------------------------------------------------------------------
__global__ __launch_bounds__(256, 2) void proj_mma(const float* __restrict__ bias,
                                                   float* __restrict__ out)
{
    extern __shared__ char smem[];
    const int n0 = blockIdx.x * 128;
    const int m0 = blockIdx.y * 128;
    const int lane = threadIdx.x & 31;
    const int wid = threadIdx.x >> 5;
    const int wm = wid >> 2, wn = wid & 3;

    float c[4][4][4];
    gemm_core(smem, g_ctx_hi, g_wproj_hi, m0, n0, c);

#pragma unroll
    for (int mf = 0; mf < 4; mf++)
#pragma unroll
        for (int nf = 0; nf < 4; nf++) {
            const int rg = m0 + wm * 64 + mf * 16 + (lane >> 2);
            const int cg = n0 + wn * 32 + nf * 8 + (lane & 3) * 2;
            const float b0 = bias[cg], b1 = bias[cg + 1];
            float2 v0 = make_float2(c[mf][nf][0] + b0, c[mf][nf][1] + b1);
            float2 v1 = make_float2(c[mf][nf][2] + b0, c[mf][nf][3] + b1);
            *reinterpret_cast<float2*>(out + (size_t)rg * CDIM + cg) = v0;
            *reinterpret_cast<float2*>(out + (size_t)(rg + 8) * CDIM + cg) = v1;
        }
}

// ---------------------------------------------------------------------------
// Flash attention (round-10 proven shape + base-2 softmax):
// grid (16, 24), 256 threads, 2 CTAs/SM, 128-row q-tile.
// smem: Qhi 18432 | 2 stages x [Khi 9216 | Vthi 9216]
// ---------------------------------------------------------------------------
#define AKV      18432
#define ASTAGE   18432
#define AV_HI    9216
#define ATTN_SMEM (AKV + 2 * ASTAGE)   // 55296

__device__ __forceinline__ void attn_load_stage(
    uint32_t sb, const __half* Kh, const __half* Vh, int kv0, int tid)
{
    const int row = tid >> 2;                 // 0..63
    const int cb  = (tid & 3) * 32;
    const uint32_t so = (uint32_t)row * 144 + cb;
    const char* kh = (const char*)(Kh + (size_t)(kv0 + row) * HDIM) + cb;
    const char* vh = (const char*)(Vh + (size_t)row * SEQ + kv0) + cb;
    cp16(sb + so, kh);            cp16(sb + so + 16, kh + 16);
    cp16(sb + AV_HI + so, vh);    cp16(sb + AV_HI + so + 16, vh + 16);
}

__global__ __launch_bounds__(256, 2) void attn_mma()
{
    extern __shared__ char smem[];
    const uint32_t sb = smem_u32(smem);
    const int q0 = blockIdx.x * 128;
    const int bh = blockIdx.y;
    const int tid = threadIdx.x;
    const int lane = tid & 31;
    const int wid = tid >> 5;

    const __half* Qh = g_q_hi + (size_t)bh * SEQ * HDIM;
    const __half* Kh = g_k_hi + (size_t)bh * SEQ * HDIM;
    const __half* Vh = g_vt_hi + (size_t)bh * HDIM * SEQ;

    // Load Q tile (144B pitch)
    {
        const int row = tid >> 1;
        const int cb = (tid & 1) * 64;
        const uint4* qs = reinterpret_cast<const uint4*>((const char*)(Qh + (size_t)(q0 + row) * HDIM) + cb);
        uint4* dh = reinterpret_cast<uint4*>(smem + (uint32_t)row * 144 + cb);
#pragma unroll
        for (int i = 0; i < 4; i++) dh[i] = qs[i];
    }
    attn_load_stage(sb + AKV, Kh, Vh, 0, tid);
    cp_commit();
    __syncthreads();

    const uint32_t a_lrow = lane % 16, a_koff = (lane >> 4) * 16;
    const uint32_t b_lrow = (lane % 8) + ((lane >> 4) << 3), b_koff = ((lane >> 3) & 1) * 16;

    uint32_t qh[4][4];
#pragma unroll
    for (int ks = 0; ks < 4; ks++) {
        uint32_t addr = sb + (uint32_t)(wid * 16 + a_lrow) * 144 + ks * 32 + a_koff;
        ldsm4(addr, qh[ks][0], qh[ks][1], qh[ks][2], qh[ks][3]);
    }

    float o[8][4];
#pragma unroll
    for (int nf = 0; nf < 8; nf++)
#pragma unroll
        for (int e = 0; e < 4; e++) o[nf][e] = 0.0f;
    float m_run0 = -1e30f, m_run1 = -1e30f, l_run0 = 0.0f, l_run1 = 0.0f;

    const int NIT = SEQ / 64;   // 32
    for (int it = 0; it < NIT; it++) {
        cp_wait<0>();
        __syncthreads();
        if (it + 1 < NIT) {
            attn_load_stage(sb + AKV + ((it + 1) & 1) * ASTAGE, Kh, Vh, (it + 1) * 64, tid);
            cp_commit();
        }
        const uint32_t st = sb + AKV + (it & 1) * ASTAGE;

        // ---- S = qh kh^T (scores in log2 domain; log2e folded into q) ----
        float s[8][4];
#pragma unroll
        for (int nf = 0; nf < 8; nf++)
#pragma unroll
            for (int e = 0; e < 4; e++) s[nf][e] = 0.0f;
#pragma unroll
        for (int ks = 0; ks < 4; ks++) {
            uint32_t kbh[8][2];
#pragma unroll
            for (int nfp = 0; nfp < 4; nfp++) {
                uint32_t addr = st + (uint32_t)(nfp * 16 + b_lrow) * 144 + ks * 32 + b_koff;
                ldsm4(addr, kbh[2 * nfp][0], kbh[2 * nfp][1], kbh[2 * nfp + 1][0], kbh[2 * nfp + 1][1]);
            }
#pragma unroll
            for (int nf = 0; nf < 8; nf++)
                mma_f32(s[nf], qh[ks], kbh[nf]);
        }

        // ---- online softmax (base-2) ----
        float vm0 = -1e30f, vm1 = -1e30f;
#pragma unroll
        for (int nf = 0; nf < 8; nf++) {
            vm0 = fmaxf(vm0, fmaxf(s[nf][0], s[nf][1]));
            vm1 = fmaxf(vm1, fmaxf(s[nf][2], s[nf][3]));
        }
        vm0 = fmaxf(vm0, __shfl_xor_sync(0xffffffff, vm0, 1));
        vm0 = fmaxf(vm0, __shfl_xor_sync(0xffffffff, vm0, 2));
        vm1 = fmaxf(vm1, __shfl_xor_sync(0xffffffff, vm1, 1));
        vm1 = fmaxf(vm1, __shfl_xor_sync(0xffffffff, vm1, 2));
        const float nm0 = fmaxf(m_run0, vm0);
        const float nm1 = fmaxf(m_run1, vm1);
        const float corr0 = fexp2(m_run0 - nm0);
        const float corr1 = fexp2(m_run1 - nm1);
        float sum0 = 0.0f, sum1 = 0.0f;
#pragma unroll
        for (int nf = 0; nf < 8; nf++) {
            s[nf][0] = fexp2(s[nf][0] - nm0); sum0 += s[nf][0];
            s[nf][1] = fexp2(s[nf][1] - nm0); sum0 += s[nf][1];
            s[nf][2] = fexp2(s[nf][2] - nm1); sum1 += s[nf][2];
            s[nf][3] = fexp2(s[nf][3] - nm1); sum1 += s[nf][3];
        }
        sum0 += __shfl_xor_sync(0xffffffff, sum0, 1);
        sum0 += __shfl_xor_sync(0xffffffff, sum0, 2);
        sum1 += __shfl_xor_sync(0xffffffff, sum1, 1);
        sum1 += __shfl_xor_sync(0xffffffff, sum1, 2);
        l_run0 = l_run0 * corr0 + sum0;
        l_run1 = l_run1 * corr1 + sum1;
        m_run0 = nm0; m_run1 = nm1;
#pragma unroll
        for (int nf = 0; nf < 8; nf++) {
            o[nf][0] *= corr0; o[nf][1] *= corr0;
            o[nf][2] *= corr1; o[nf][3] *= corr1;
        }

        // ---- O += p16 · vh ----
#pragma unroll
        for (int ks2 = 0; ks2 < 4; ks2++) {
            uint32_t pah[4];
            pah[0] = pack2h(s[2 * ks2][0],     s[2 * ks2][1]);
            pah[1] = pack2h(s[2 * ks2][2],     s[2 * ks2][3]);
            pah[2] = pack2h(s[2 * ks2 + 1][0], s[2 * ks2 + 1][1]);
            pah[3] = pack2h(s[2 * ks2 + 1][2], s[2 * ks2 + 1][3]);
            uint32_t vbh[8][2];
#pragma unroll
            for (int nfp = 0; nfp < 4; nfp++) {
                uint32_t addr = st + AV_HI + (uint32_t)(nfp * 16 + b_lrow) * 144 + ks2 * 32 + b_koff;
                ldsm4(addr, vbh[2 * nfp][0], vbh[2 * nfp][1], vbh[2 * nfp + 1][0], vbh[2 * nfp + 1][1]);
            }
#pragma unroll
            for (int nf = 0; nf < 8; nf++)
                mma_f32(o[nf], pah, vbh[nf]);
        }
    }

    // ---- epilogue ----
    const int b = bh / HEADS;
    const int h = bh % HEADS;
    const float inv0 = 1.0f / l_run0;
    const float inv1 = 1.0f / l_run1;
    const int r0 = q0 + wid * 16 + (lane >> 2);
#pragma unroll
    for (int nf = 0; nf < 8; nf++) {
        const int d = nf * 8 + (lane & 3) * 2;
        size_t off = ((size_t)(b * SEQ + r0)) * CDIM + h * HDIM + d;
        *reinterpret_cast<uint32_t*>(g_ctx_hi + off) = pack2h(o[nf][0] * inv0, o[nf][1] * inv0);
        off = ((size_t)(b * SEQ + r0 + 8)) * CDIM + h * HDIM + d;
        *reinterpret_cast<uint32_t*>(g_ctx_hi + off) = pack2h(o[nf][2] * inv1, o[nf][3] * inv1);
    }
}

// ---------------------------------------------------------------------------
// Launch
// ---------------------------------------------------------------------------
extern "C" void kernel_launch(void* const* d_in, const int* in_sizes, int n_in,
                              void* d_out, int out_size)
{
    const float* x      = (const float*)d_in[0];
    const float* w_qkv  = (const float*)d_in[1];
    const float* w_proj = (const float*)d_in[2];
    const float* b_proj = (const float*)d_in[3];
    float* out = (float*)d_out;
    (void)in_sizes; (void)n_in; (void)out_size;

    cudaFuncSetAttribute(qkv_mma,  cudaFuncAttributeMaxDynamicSharedMemorySize, GEMM_SMEM);
    cudaFuncSetAttribute(attn_mma, cudaFuncAttributeMaxDynamicSharedMemorySize, ATTN_SMEM);
    cudaFuncSetAttribute(proj_mma, cudaFuncAttributeMaxDynamicSharedMemorySize, GEMM_SMEM);

    __half *xh, *wh, *ph;
    cudaGetSymbolAddress((void**)&xh, g_x_hi);
    cudaGetSymbolAddress((void**)&wh, g_wqkv_hi);
    cudaGetSymbolAddress((void**)&ph, g_wproj_hi);

    convert_all<<<1024, 256>>>(x, xh, MROWS * CDIM,
                               w_qkv, wh, QKV_N * CDIM,
                               w_proj, ph, CDIM * CDIM);

    qkv_mma<<<dim3(QKV_N / 128, MROWS / 128), 256, GEMM_SMEM>>>();
    attn_mma<<<dim3(SEQ / 128, BH), 256, ATTN_SMEM>>>();
    proj_mma<<<dim3(CDIM / 128, MROWS / 128), 256, GEMM_SMEM>>>(b_proj, out);
}

// round 17
// speedup vs baseline: 1.3278x; 1.0306x over previous
#include <cuda_runtime.h>
#include <cuda_fp16.h>
#include <cstdint>

#define BATCH   2
#define SEQ     2048
#define CDIM    768
#define HEADS   12
#define HDIM    64
#define QKV_N   2304
#define MROWS   4096
#define BH      24
#define SCALEF  0.125f
#define LOG2E   1.4426950408889634f

// ---------------------------------------------------------------------------
// Scratch (pure fp16)
// ---------------------------------------------------------------------------
__device__ __half g_x_hi[MROWS * CDIM];
__device__ __half g_wqkv_hi[QKV_N * CDIM];
__device__ __half g_wproj_hi[CDIM * CDIM];
__device__ __half g_q_hi[BH * SEQ * HDIM];    // [b,h,n,d], pre-scaled by log2e/8
__device__ __half g_k_hi[BH * SEQ * HDIM];
__device__ __half g_vt_hi[BH * HDIM * SEQ];   // [b,h,d,n]
__device__ __half g_ctx_hi[MROWS * CDIM];

// ---------------------------------------------------------------------------
// Helpers
// ---------------------------------------------------------------------------
__device__ __forceinline__ uint32_t smem_u32(const void* p) {
    uint32_t a;
    asm("{ .reg .u64 t; cvta.to.shared.u64 t, %1; cvt.u32.u64 %0, t; }" : "=r"(a) : "l"(p));
    return a;
}
__device__ __forceinline__ void cp16(uint32_t dst, const void* src) {
    asm volatile("cp.async.cg.shared.global [%0], [%1], 16;" :: "r"(dst), "l"(src));
}
__device__ __forceinline__ void cp_commit() { asm volatile("cp.async.commit_group;"); }
template <int N> __device__ __forceinline__ void cp_wait() {
    asm volatile("cp.async.wait_group %0;" :: "n"(N));
}
__device__ __forceinline__ void ldsm4(uint32_t a, uint32_t& r0, uint32_t& r1, uint32_t& r2, uint32_t& r3) {
    asm volatile("ldmatrix.sync.aligned.m8n8.x4.shared.b16 {%0,%1,%2,%3}, [%4];"
                 : "=r"(r0), "=r"(r1), "=r"(r2), "=r"(r3) : "r"(a));
}
__device__ __forceinline__ void mma_f32(float* c, const uint32_t* a, const uint32_t* b) {
    asm volatile("mma.sync.aligned.m16n8k16.row.col.f32.f16.f16.f32 "
                 "{%0,%1,%2,%3}, {%4,%5,%6,%7}, {%8,%9}, {%0,%1,%2,%3};"
                 : "+f"(c[0]), "+f"(c[1]), "+f"(c[2]), "+f"(c[3])
                 : "r"(a[0]), "r"(a[1]), "r"(a[2]), "r"(a[3]), "r"(b[0]), "r"(b[1]));
}
__device__ __forceinline__ uint32_t pack2h(float x, float y) {
    __half2 H = __halves2half2(__float2half_rn(x), __float2half_rn(y));
    return *reinterpret_cast<uint32_t*>(&H);
}
__device__ __forceinline__ float fexp2(float x) {
    float r;
    asm("ex2.approx.f32 %0, %1;" : "=f"(r) : "f"(x));
    return r;
}

// ---------------------------------------------------------------------------
// Converts: one launch covers all three arrays
// ---------------------------------------------------------------------------
__global__ void convert_all(const float* __restrict__ s0, __half* __restrict__ d0, int n0,
                            const float* __restrict__ s1, __half* __restrict__ d1, int n1,
                            const float* __restrict__ s2, __half* __restrict__ d2, int n2)
{
    const int ntot = n0 + n1 + n2;
    for (int i = blockIdx.x * blockDim.x + threadIdx.x; i < ntot; i += gridDim.x * blockDim.x) {
        if (i < n0)               d0[i] = __float2half_rn(s0[i]);
        else if (i < n0 + n1)     d1[i - n0] = __float2half_rn(s1[i - n0]);
        else                      d2[i - n0 - n1] = __float2half_rn(s2[i - n0 - n1]);
    }
}

// ---------------------------------------------------------------------------
// GEMM core (round-10 proven shape): C(128x128) = Ah Bh^T over K=768,
// K-chunk 32, 2-stage pipeline. 256 threads, warp tile 64x32. 80B row pitch.
// ---------------------------------------------------------------------------
#define GSTAGE   20480
#define G_BHI    10240
#define GEMM_SMEM (2 * GSTAGE)

__device__ __forceinline__ void gemm_load_stage(
    uint32_t sb, const __half* Ahi, const __half* Bhi,
    int m0, int n0, int k0, int tid)
{
    const int row = tid >> 1;
    const int cb  = (tid & 1) * 32;
    const size_t ga = (size_t)(m0 + row) * CDIM + k0;
    const size_t gb = (size_t)(n0 + row) * CDIM + k0;
    const uint32_t so = (uint32_t)row * 80 + cb;
    cp16(sb + so,               (const char*)(Ahi + ga) + cb);
    cp16(sb + so + 16,          (const char*)(Ahi + ga) + cb + 16);
    cp16(sb + G_BHI + so,       (const char*)(Bhi + gb) + cb);
    cp16(sb + G_BHI + so + 16,  (const char*)(Bhi + gb) + cb + 16);
}

__device__ __forceinline__ void ld_afrag(uint32_t st, int wm, int step,
                                         uint32_t a_lrow, uint32_t a_koff, uint32_t* a)
{
    const int ks = step >> 2, mf = step & 3;
    uint32_t addr = st + (uint32_t)(wm * 64 + mf * 16 + a_lrow) * 80 + ks * 32 + a_koff;
    ldsm4(addr, a[0], a[1], a[2], a[3]);
}
__device__ __forceinline__ void ld_bfrag(uint32_t st, int wn, int ks,
                                         uint32_t b_lrow, uint32_t b_koff,
                                         uint32_t bh[4][2])
{
#pragma unroll
    for (int nfp = 0; nfp < 2; nfp++) {
        uint32_t addr = st + G_BHI + (uint32_t)(wn * 32 + nfp * 16 + b_lrow) * 80 + ks * 32 + b_koff;
        ldsm4(addr, bh[2 * nfp][0], bh[2 * nfp][1], bh[2 * nfp + 1][0], bh[2 * nfp + 1][1]);
    }
}

__device__ __forceinline__ void gemm_core(
    char* smem, const __half* Ahi, const __half* Bhi,
    int m0, int n0, float c[4][4][4])
{
    const int tid = threadIdx.x;
    const int lane = tid & 31;
    const int wid = tid >> 5;
    const int wm = wid >> 2, wn = wid & 3;
    const uint32_t sb = smem_u32(smem);

    const uint32_t a_lrow = lane % 16, a_koff = (lane >> 4) * 16;
    const uint32_t b_lrow = (lane % 8) + ((lane >> 4) << 3), b_koff = ((lane >> 3) & 1) * 16;

#pragma unroll
    for (int i = 0; i < 4; i++)
#pragma unroll
        for (int j = 0; j < 4; j++)
#pragma unroll
            for (int e = 0; e < 4; e++) c[i][j][e] = 0.0f;

    gemm_load_stage(sb, Ahi, Bhi, m0, n0, 0, tid);
    cp_commit();

    uint32_t ar[2][4];
    uint32_t bhr[2][4][2];

    for (int it = 0; it < 24; it++) {
        cp_wait<0>();
        __syncthreads();
        if (it + 1 < 24) {
            gemm_load_stage(sb + ((it + 1) & 1) * GSTAGE, Ahi, Bhi, m0, n0, (it + 1) * 32, tid);
            cp_commit();
        }
        const uint32_t st = sb + (it & 1) * GSTAGE;

        ld_bfrag(st, wn, 0, b_lrow, b_koff, bhr[0]);
        ld_afrag(st, wm, 0, a_lrow, a_koff, ar[0]);

#pragma unroll
        for (int ks = 0; ks < 2; ks++) {
            if (ks == 0)
                ld_bfrag(st, wn, 1, b_lrow, b_koff, bhr[1]);
#pragma unroll
            for (int mf = 0; mf < 4; mf++) {
                const int step = ks * 4 + mf;
                if (step + 1 < 8)
                    ld_afrag(st, wm, step + 1, a_lrow, a_koff, ar[(step + 1) & 1]);
                const uint32_t* a = ar[step & 1];
#pragma unroll
                for (int nf = 0; nf < 4; nf++)
                    mma_f32(c[mf][nf], a, bhr[ks][nf]);
            }
        }
    }
}

// ---------------------------------------------------------------------------
// QKV GEMM: grid (18, 32), 256 threads, 2 CTAs/SM
// ---------------------------------------------------------------------------
__device__ __forceinline__ void qkv_store(int s, int rowg, int colg, float v0, float v1)
{
    const int b = rowg >> 11, n = rowg & 2047;
    const int rem = colg - s * CDIM;
    const int h = rem >> 6, d = rem & 63;
    if (s == 0) {
        const float qs = SCALEF * LOG2E;    // fold softmax scale + log2e into q
        const size_t off = ((size_t)(b * HEADS + h) * SEQ + n) * HDIM + d;
        *reinterpret_cast<uint32_t*>(g_q_hi + off) = pack2h(v0 * qs, v1 * qs);
    } else if (s == 1) {
        const size_t off = ((size_t)(b * HEADS + h) * SEQ + n) * HDIM + d;
        *reinterpret_cast<uint32_t*>(g_k_hi + off) = pack2h(v0, v1);
    } else {
        const size_t base = ((size_t)(b * HEADS + h) * HDIM) * SEQ;
        g_vt_hi[base + (size_t)d * SEQ + n]       = __float2half_rn(v0);
        g_vt_hi[base + (size_t)(d + 1) * SEQ + n] = __float2half_rn(v1);
    }
}

__global__ __launch_bounds__(256, 2) void qkv_mma()
{
    extern __shared__ char smem[];
    const int n0 = blockIdx.x * 128;
    const int m0 = blockIdx.y * 128;
    const int lane = threadIdx.x & 31;
    const int wid = threadIdx.x >> 5;
    const int wm = wid >> 2, wn = wid & 3;

    float c[4][4][4];
    gemm_core(smem, g_x_hi, g_wqkv_hi, m0, n0, c);

    const int s = n0 / CDIM;
#pragma unroll
    for (int mf = 0; mf < 4; mf++)
#pragma unroll
        for (int nf = 0; nf < 4; nf++) {
            const int rg = m0 + wm * 64 + mf * 16 + (lane >> 2);
            const int cg = n0 + wn * 32 + nf * 8 + (lane & 3) * 2;
            qkv_store(s, rg,     cg, c[mf][nf][0], c[mf][nf][1]);
            qkv_store(s, rg + 8, cg, c[mf][nf][2], c[mf][nf][3]);
        }
}

// ---------------------------------------------------------------------------
// Output projection: 64-row M tiles for single-wave latency.
// grid (6, 64) = 384 CTAs, 256 threads, warp tile 32x32, 3 CTAs/SM.
// smem stage: [A 64x80 = 5120][B 128x80 = 10240] = 15360; 2 stages.
// ---------------------------------------------------------------------------
#define P_B      5120
#define PSTAGE   15360
#define PROJ_SMEM (2 * PSTAGE)

__device__ __forceinline__ void proj_load_stage(
    uint32_t sb, const __half* Ahi, const __half* Bhi,
    int m0, int n0, int k0, int tid)
{
    // A: 64 rows, 4 threads/row x 16B
    {
        const int row = tid >> 2;
        const int cb  = (tid & 3) * 16;
        const size_t ga = (size_t)(m0 + row) * CDIM + k0;
        cp16(sb + (uint32_t)row * 80 + cb, (const char*)(Ahi + ga) + cb);
    }
    // B: 128 rows, 2 threads/row x 32B
    {
        const int row = tid >> 1;
        const int cb  = (tid & 1) * 32;
        const size_t gb = (size_t)(n0 + row) * CDIM + k0;
        const uint32_t so = P_B + (uint32_t)row * 80 + cb;
        cp16(sb + so,      (const char*)(Bhi + gb) + cb);
        cp16(sb + so + 16, (const char*)(Bhi + gb) + cb + 16);
    }
}

__global__ __launch_bounds__(256, 3) void proj_mma(const float* __restrict__ bias,
                                                   float* __restrict__ out)
{
    extern __shared__ char smem[];
    const int n0 = blockIdx.x * 128;
    const int m0 = blockIdx.y * 64;
    const int tid = threadIdx.x;
    const int lane = tid & 31;
    const int wid = tid >> 5;
    const int wm = wid >> 2, wn = wid & 3;      // 2 x 4 warp grid, warp tile 32x32
    const uint32_t sb = smem_u32(smem);

    const uint32_t a_lrow = lane % 16, a_koff = (lane >> 4) * 16;
    const uint32_t b_lrow = (lane % 8) + ((lane >> 4) << 3), b_koff = ((lane >> 3) & 1) * 16;

    float c[2][4][4];
#pragma unroll
    for (int i = 0; i < 2; i++)
#pragma unroll
        for (int j = 0; j < 4; j++)
#pragma unroll
            for (int e = 0; e < 4; e++) c[i][j][e] = 0.0f;

    proj_load_stage(sb, g_ctx_hi, g_wproj_hi, m0, n0, 0, tid);
    cp_commit();

    for (int it = 0; it < 24; it++) {
        cp_wait<0>();
        __syncthreads();
        if (it + 1 < 24) {
            proj_load_stage(sb + ((it + 1) & 1) * PSTAGE, g_ctx_hi, g_wproj_hi,
                            m0, n0, (it + 1) * 32, tid);
            cp_commit();
        }
        const uint32_t st = sb + (it & 1) * PSTAGE;

#pragma unroll
        for (int ks = 0; ks < 2; ks++) {
            uint32_t bh[4][2];
#pragma unroll
            for (int nfp = 0; nfp < 2; nfp++) {
                uint32_t addr = st + P_B + (uint32_t)(wn * 32 + nfp * 16 + b_lrow) * 80 + ks * 32 + b_koff;
                ldsm4(addr, bh[2 * nfp][0], bh[2 * nfp][1], bh[2 * nfp + 1][0], bh[2 * nfp + 1][1]);
            }
#pragma unroll
            for (int mf = 0; mf < 2; mf++) {
                uint32_t a[4];
                uint32_t addr = st + (uint32_t)(wm * 32 + mf * 16 + a_lrow) * 80 + ks * 32 + a_koff;
                ldsm4(addr, a[0], a[1], a[2], a[3]);
#pragma unroll
                for (int nf = 0; nf < 4; nf++)
                    mma_f32(c[mf][nf], a, bh[nf]);
            }
        }
    }

#pragma unroll
    for (int mf = 0; mf < 2; mf++)
#pragma unroll
        for (int nf = 0; nf < 4; nf++) {
            const int rg = m0 + wm * 32 + mf * 16 + (lane >> 2);
            const int cg = n0 + wn * 32 + nf * 8 + (lane & 3) * 2;
            const float b0 = bias[cg], b1 = bias[cg + 1];
            float2 v0 = make_float2(c[mf][nf][0] + b0, c[mf][nf][1] + b1);
            float2 v1 = make_float2(c[mf][nf][2] + b0, c[mf][nf][3] + b1);
            *reinterpret_cast<float2*>(out + (size_t)rg * CDIM + cg) = v0;
            *reinterpret_cast<float2*>(out + (size_t)(rg + 8) * CDIM + cg) = v1;
        }
}

// ---------------------------------------------------------------------------
// Flash attention (round-10 proven shape + base-2 softmax):
// grid (16, 24), 256 threads, 2 CTAs/SM, 128-row q-tile.
// smem: Qhi 18432 | 2 stages x [Khi 9216 | Vthi 9216]
// ---------------------------------------------------------------------------
#define AKV      18432
#define ASTAGE   18432
#define AV_HI    9216
#define ATTN_SMEM (AKV + 2 * ASTAGE)   // 55296

__device__ __forceinline__ void attn_load_stage(
    uint32_t sb, const __half* Kh, const __half* Vh, int kv0, int tid)
{
    const int row = tid >> 2;                 // 0..63
    const int cb  = (tid & 3) * 32;
    const uint32_t so = (uint32_t)row * 144 + cb;
    const char* kh = (const char*)(Kh + (size_t)(kv0 + row) * HDIM) + cb;
    const char* vh = (const char*)(Vh + (size_t)row * SEQ + kv0) + cb;
    cp16(sb + so, kh);            cp16(sb + so + 16, kh + 16);
    cp16(sb + AV_HI + so, vh);    cp16(sb + AV_HI + so + 16, vh + 16);
}

__global__ __launch_bounds__(256, 2) void attn_mma()
{
    extern __shared__ char smem[];
    const uint32_t sb = smem_u32(smem);
    const int q0 = blockIdx.x * 128;
    const int bh = blockIdx.y;
    const int tid = threadIdx.x;
    const int lane = tid & 31;
    const int wid = tid >> 5;

    const __half* Qh = g_q_hi + (size_t)bh * SEQ * HDIM;
    const __half* Kh = g_k_hi + (size_t)bh * SEQ * HDIM;
    const __half* Vh = g_vt_hi + (size_t)bh * HDIM * SEQ;

    // Load Q tile (144B pitch)
    {
        const int row = tid >> 1;
        const int cb = (tid & 1) * 64;
        const uint4* qs = reinterpret_cast<const uint4*>((const char*)(Qh + (size_t)(q0 + row) * HDIM) + cb);
        uint4* dh = reinterpret_cast<uint4*>(smem + (uint32_t)row * 144 + cb);
#pragma unroll
        for (int i = 0; i < 4; i++) dh[i] = qs[i];
    }
    attn_load_stage(sb + AKV, Kh, Vh, 0, tid);
    cp_commit();
    __syncthreads();

    const uint32_t a_lrow = lane % 16, a_koff = (lane >> 4) * 16;
    const uint32_t b_lrow = (lane % 8) + ((lane >> 4) << 3), b_koff = ((lane >> 3) & 1) * 16;

    uint32_t qh[4][4];
#pragma unroll
    for (int ks = 0; ks < 4; ks++) {
        uint32_t addr = sb + (uint32_t)(wid * 16 + a_lrow) * 144 + ks * 32 + a_koff;
        ldsm4(addr, qh[ks][0], qh[ks][1], qh[ks][2], qh[ks][3]);
    }

    float o[8][4];
#pragma unroll
    for (int nf = 0; nf < 8; nf++)
#pragma unroll
        for (int e = 0; e < 4; e++) o[nf][e] = 0.0f;
    float m_run0 = -1e30f, m_run1 = -1e30f, l_run0 = 0.0f, l_run1 = 0.0f;

    const int NIT = SEQ / 64;   // 32
    for (int it = 0; it < NIT; it++) {
        cp_wait<0>();
        __syncthreads();
        if (it + 1 < NIT) {
            attn_load_stage(sb + AKV + ((it + 1) & 1) * ASTAGE, Kh, Vh, (it + 1) * 64, tid);
            cp_commit();
        }
        const uint32_t st = sb + AKV + (it & 1) * ASTAGE;

        // ---- S = qh kh^T (scores in log2 domain; log2e folded into q) ----
        float s[8][4];
#pragma unroll
        for (int nf = 0; nf < 8; nf++)
#pragma unroll
            for (int e = 0; e < 4; e++) s[nf][e] = 0.0f;
#pragma unroll
        for (int ks = 0; ks < 4; ks++) {
            uint32_t kbh[8][2];
#pragma unroll
            for (int nfp = 0; nfp < 4; nfp++) {
                uint32_t addr = st + (uint32_t)(nfp * 16 + b_lrow) * 144 + ks * 32 + b_koff;
                ldsm4(addr, kbh[2 * nfp][0], kbh[2 * nfp][1], kbh[2 * nfp + 1][0], kbh[2 * nfp + 1][1]);
            }
#pragma unroll
            for (int nf = 0; nf < 8; nf++)
                mma_f32(s[nf], qh[ks], kbh[nf]);
        }

        // ---- online softmax (base-2) ----
        float vm0 = -1e30f, vm1 = -1e30f;
#pragma unroll
        for (int nf = 0; nf < 8; nf++) {
            vm0 = fmaxf(vm0, fmaxf(s[nf][0], s[nf][1]));
            vm1 = fmaxf(vm1, fmaxf(s[nf][2], s[nf][3]));
        }
        vm0 = fmaxf(vm0, __shfl_xor_sync(0xffffffff, vm0, 1));
        vm0 = fmaxf(vm0, __shfl_xor_sync(0xffffffff, vm0, 2));
        vm1 = fmaxf(vm1, __shfl_xor_sync(0xffffffff, vm1, 1));
        vm1 = fmaxf(vm1, __shfl_xor_sync(0xffffffff, vm1, 2));
        const float nm0 = fmaxf(m_run0, vm0);
        const float nm1 = fmaxf(m_run1, vm1);
        const float corr0 = fexp2(m_run0 - nm0);
        const float corr1 = fexp2(m_run1 - nm1);
        float sum0 = 0.0f, sum1 = 0.0f;
#pragma unroll
        for (int nf = 0; nf < 8; nf++) {
            s[nf][0] = fexp2(s[nf][0] - nm0); sum0 += s[nf][0];
            s[nf][1] = fexp2(s[nf][1] - nm0); sum0 += s[nf][1];
            s[nf][2] = fexp2(s[nf][2] - nm1); sum1 += s[nf][2];
            s[nf][3] = fexp2(s[nf][3] - nm1); sum1 += s[nf][3];
        }
        sum0 += __shfl_xor_sync(0xffffffff, sum0, 1);
        sum0 += __shfl_xor_sync(0xffffffff, sum0, 2);
        sum1 += __shfl_xor_sync(0xffffffff, sum1, 1);
        sum1 += __shfl_xor_sync(0xffffffff, sum1, 2);
        l_run0 = l_run0 * corr0 + sum0;
        l_run1 = l_run1 * corr1 + sum1;
        m_run0 = nm0; m_run1 = nm1;
#pragma unroll
        for (int nf = 0; nf < 8; nf++) {
            o[nf][0] *= corr0; o[nf][1] *= corr0;
            o[nf][2] *= corr1; o[nf][3] *= corr1;
        }

        // ---- O += p16 · vh ----
#pragma unroll
        for (int ks2 = 0; ks2 < 4; ks2++) {
            uint32_t pah[4];
            pah[0] = pack2h(s[2 * ks2][0],     s[2 * ks2][1]);
            pah[1] = pack2h(s[2 * ks2][2],     s[2 * ks2][3]);
            pah[2] = pack2h(s[2 * ks2 + 1][0], s[2 * ks2 + 1][1]);
            pah[3] = pack2h(s[2 * ks2 + 1][2], s[2 * ks2 + 1][3]);
            uint32_t vbh[8][2];
#pragma unroll
            for (int nfp = 0; nfp < 4; nfp++) {
                uint32_t addr = st + AV_HI + (uint32_t)(nfp * 16 + b_lrow) * 144 + ks2 * 32 + b_koff;
                ldsm4(addr, vbh[2 * nfp][0], vbh[2 * nfp][1], vbh[2 * nfp + 1][0], vbh[2 * nfp + 1][1]);
            }
#pragma unroll
            for (int nf = 0; nf < 8; nf++)
                mma_f32(o[nf], pah, vbh[nf]);
        }
    }

    // ---- epilogue ----
    const int b = bh / HEADS;
    const int h = bh % HEADS;
    const float inv0 = 1.0f / l_run0;
    const float inv1 = 1.0f / l_run1;
    const int r0 = q0 + wid * 16 + (lane >> 2);
#pragma unroll
    for (int nf = 0; nf < 8; nf++) {
        const int d = nf * 8 + (lane & 3) * 2;
        size_t off = ((size_t)(b * SEQ + r0)) * CDIM + h * HDIM + d;
        *reinterpret_cast<uint32_t*>(g_ctx_hi + off) = pack2h(o[nf][0] * inv0, o[nf][1] * inv0);
        off = ((size_t)(b * SEQ + r0 + 8)) * CDIM + h * HDIM + d;
        *reinterpret_cast<uint32_t*>(g_ctx_hi + off) = pack2h(o[nf][2] * inv1, o[nf][3] * inv1);
    }
}

// ---------------------------------------------------------------------------
// Launch
// ---------------------------------------------------------------------------
extern "C" void kernel_launch(void* const* d_in, const int* in_sizes, int n_in,
                              void* d_out, int out_size)
{
    const float* x      = (const float*)d_in[0];
    const float* w_qkv  = (const float*)d_in[1];
    const float* w_proj = (const float*)d_in[2];
    const float* b_proj = (const float*)d_in[3];
    float* out = (float*)d_out;
    (void)in_sizes; (void)n_in; (void)out_size;

    cudaFuncSetAttribute(qkv_mma,  cudaFuncAttributeMaxDynamicSharedMemorySize, GEMM_SMEM);
    cudaFuncSetAttribute(attn_mma, cudaFuncAttributeMaxDynamicSharedMemorySize, ATTN_SMEM);
    cudaFuncSetAttribute(proj_mma, cudaFuncAttributeMaxDynamicSharedMemorySize, PROJ_SMEM);

    __half *xh, *wh, *ph;
    cudaGetSymbolAddress((void**)&xh, g_x_hi);
    cudaGetSymbolAddress((void**)&wh, g_wqkv_hi);
    cudaGetSymbolAddress((void**)&ph, g_wproj_hi);

    convert_all<<<1024, 256>>>(x, xh, MROWS * CDIM,
                               w_qkv, wh, QKV_N * CDIM,
                               w_proj, ph, CDIM * CDIM);

    qkv_mma<<<dim3(QKV_N / 128, MROWS / 128), 256, GEMM_SMEM>>>();
    attn_mma<<<dim3(SEQ / 128, BH), 256, ATTN_SMEM>>>();
    proj_mma<<<dim3(CDIM / 128, MROWS / 64), 256, PROJ_SMEM>>>(b_proj, out);
}